// round 14
// baseline (speedup 1.0000x reference)
#include <cuda_runtime.h>
#include <cuda_fp16.h>
#include <cstdint>

#define Bsz 4
#define Cin 64
#define OUTC 64
#define H 256
#define W 256
#define HW (H*W)

#define MTILE 128          // deform pixels per CTA (half row)
#define SH 72              // stride in halves (64 + 8 pad) -> conflict-free
#define SH32 (SH/2)        // = 36 u32 per row

#define OJ 24              // offset channels 18 padded to 24
#define OHPX 258           // offsets A-halo pixels: -1 .. 256

// Scratch (device globals — no allocation allowed)
__device__ float g_offs[(size_t)Bsz * 18 * HW];        // offset conv output (fp32-accurate)
__device__ __half g_wh[9 * OUTC * Cin];                // w_def -> [k][o][c] fp16
__device__ __half g_xh[(size_t)Bsz * HW * Cin];        // x NHWC fp16 hi (33.5MB)
__device__ __half g_xl[(size_t)Bsz * HW * Cin];        // x NHWC fp16 lo (33.5MB)
__device__ __half g_wo_hi[9 * OJ * Cin];               // w_off split hi [k][j][c]
__device__ __half g_wo_lo[9 * OJ * Cin];               // w_off split lo [k][j][c]

// ---------------------------------------------------------------------------
// helpers
// ---------------------------------------------------------------------------
__device__ __forceinline__ void mma_f16(float* d, const uint32_t* a, const uint32_t* b) {
    asm volatile(
        "mma.sync.aligned.m16n8k16.row.col.f32.f16.f16.f32 "
        "{%0,%1,%2,%3}, {%4,%5,%6,%7}, {%8,%9}, {%0,%1,%2,%3};"
        : "+f"(d[0]), "+f"(d[1]), "+f"(d[2]), "+f"(d[3])
        : "r"(a[0]), "r"(a[1]), "r"(a[2]), "r"(a[3]),
          "r"(b[0]), "r"(b[1]));
}

__device__ __forceinline__ uint32_t pack_f16x2(float lo, float hi) {
    uint32_t r;
    asm("cvt.rn.f16x2.f32 %0, %1, %2;" : "=r"(r) : "f"(hi), "f"(lo));
    return r;
}

__device__ __forceinline__ uint32_t bil4(uint32_t a, uint32_t b, uint32_t c, uint32_t d,
                                         __half2 w00, __half2 w01, __half2 w10, __half2 w11) {
    __half2 r = __hmul2(*(__half2*)&a, w00);
    r = __hfma2(*(__half2*)&b, w01, r);
    r = __hfma2(*(__half2*)&c, w10, r);
    r = __hfma2(*(__half2*)&d, w11, r);
    return *(uint32_t*)&r;
}

// ---------------------------------------------------------------------------
// Kernel 0a: w_def [o][c][ki][kj] -> g_wh[k][o][c] (fp16)
// ---------------------------------------------------------------------------
__global__ void prep_wdef_kernel(const float* __restrict__ w_def) {
    int idx = blockIdx.x * 256 + threadIdx.x;
    if (idx >= 9 * OUTC * Cin) return;
    int k = idx / (OUTC * Cin);
    int rem = idx - k * (OUTC * Cin);
    int o = rem / Cin;
    int c = rem - o * Cin;
    g_wh[idx] = __float2half_rn(w_def[(o * Cin + c) * 9 + k]);
}

// ---------------------------------------------------------------------------
// Kernel 0b: w_off [j][c][ki][kj] -> g_wo_{hi,lo}[k][j][c] fp16 split
// ---------------------------------------------------------------------------
__global__ void prep_woff_kernel(const float* __restrict__ w_off) {
    int idx = blockIdx.x * 256 + threadIdx.x;      // 13824
    if (idx >= 9 * OJ * Cin) return;
    int k = idx / (OJ * Cin);
    int rem = idx - k * (OJ * Cin);
    int j = rem / Cin;
    int c = rem - j * Cin;
    float v = (j < 18) ? w_off[((size_t)j * Cin + c) * 9 + k] : 0.f;
    __half hi = __float2half_rn(v);
    float lo = v - __half2float(hi);
    g_wo_hi[idx] = hi;
    g_wo_lo[idx] = __float2half_rn(lo);
}

// ---------------------------------------------------------------------------
// Kernel 0c: transpose x NCHW -> NHWC fp16 split (g_xh + g_xl)
// ---------------------------------------------------------------------------
__global__ void __launch_bounds__(256) transpose_x_kernel(const float* __restrict__ x) {
    __shared__ float t[Cin][33];
    int tid = threadIdx.x;
    int bx = blockIdx.x;
    int wt = (bx & 7) << 5;
    int h = (bx >> 3) & (H - 1);
    int b = bx >> 11;

    const float* xb = x + (size_t)b * Cin * HW + h * W + wt;
#pragma unroll
    for (int it = 0; it < 8; it++) {
        int c = it * 8 + (tid >> 5);
        int w = tid & 31;
        t[c][w] = xb[(size_t)c * HW + w];
    }
    __syncthreads();
    size_t base = ((size_t)(b * H + h) * W + wt) * Cin;
    uint32_t* xh = (uint32_t*)(g_xh + base);
    uint32_t* xl = (uint32_t*)(g_xl + base);
#pragma unroll
    for (int it = 0; it < 4; it++) {
        int w = it * 8 + (tid >> 5);
        int c2 = tid & 31;
        float a0 = t[2 * c2][w];
        float a1 = t[2 * c2 + 1][w];
        __half h0 = __float2half_rn(a0);
        __half h1 = __float2half_rn(a1);
        __half2 hp = __halves2half2(h0, h1);
        float l0 = a0 - __half2float(h0);
        float l1 = a1 - __half2float(h1);
        xh[w * (Cin / 2) + c2] = *(uint32_t*)&hp;
        xl[w * (Cin / 2) + c2] = pack_f16x2(l0, l1);
    }
}

// ---------------------------------------------------------------------------
// Kernel 1: offsets conv, fp16 split MMA, row-reuse, FULL 256-px row per CTA.
// Warp = 32 px (2 x m16) x 24 oc; B frags loaded once per (kk,ni), reused
// across both m-tiles. Arithmetic per pixel identical to R12.
// ---------------------------------------------------------------------------
#define OFF_SSM_U32 (OHPX * SH32)                   // 9288 per half
#define OFF_WTAP_U32 (2 * OJ * SH32)                // 1728 per tap (hi+lo)
#define OFF_DSMEM ((2 * OFF_SSM_U32 + 2 * OFF_WTAP_U32) * 4)   // 88128 B

__global__ void __launch_bounds__(256, 2) offsets_kernel(
    const float* __restrict__ b_off)
{
    extern __shared__ uint32_t dsm[];
    uint32_t* ssm_h = dsm;                              // [258 px][c] hi
    uint32_t* ssm_l = ssm_h + OFF_SSM_U32;              // lo
    uint32_t* wbuf = ssm_l + OFF_SSM_U32;               // 2 x (hi 864 | lo 864)

    int tid = threadIdx.x;
    int bx = blockIdx.x;
    int h = bx & (H - 1);
    int b = bx >> 8;

    int lane = tid & 31;
    int wid = tid >> 5;
    int r = lane & 3;
    int g = lane >> 2;
    int px0 = wid << 5;                // warp's 32-px m-tile

    float acc[2][3][4];
#pragma unroll
    for (int mi = 0; mi < 2; mi++)
#pragma unroll
        for (int ni = 0; ni < 3; ni++)
#pragma unroll
            for (int q = 0; q < 4; q++) acc[mi][ni][q] = 0.f;

    const uint4* xh4 = (const uint4*)(g_xh + (size_t)b * HW * Cin);
    const uint4* xl4 = (const uint4*)(g_xl + (size_t)b * HW * Cin);

    auto stageB = [&](int k, int buf) {
        uint32_t* wh = wbuf + buf * OFF_WTAP_U32;
        uint32_t* wl = wh + OJ * SH32;
        const uint4* sh = (const uint4*)(g_wo_hi + (size_t)k * OJ * Cin);
        const uint4* sl = (const uint4*)(g_wo_lo + (size_t)k * OJ * Cin);
        for (int i = tid; i < 2 * OJ * Cin / 8; i += 256) {
            int hf = (i >= OJ * Cin / 8);
            int ii = i - hf * (OJ * Cin / 8);
            int j = ii >> 3;
            int c8 = ii & 7;
            uint4 v = hf ? sl[ii] : sh[ii];
            *(uint4*)((hf ? wl : wh) + j * SH32 + c8 * 4) = v;
        }
    };

    auto mmaTap = [&](int t, int buf) {   // t = dx+1: A row = px + t
        uint32_t* wh = wbuf + buf * OFF_WTAP_U32;
        uint32_t* wl = wh + OJ * SH32;
#pragma unroll
        for (int kk = 0; kk < 4; kk++) {
            int kb = kk << 3;
            uint32_t ah[2][4], al[2][4];
#pragma unroll
            for (int mi = 0; mi < 2; mi++) {
                const uint32_t* arh = ssm_h + (px0 + 16 * mi + g + t) * SH32 + kb + r;
                const uint32_t* arl = ssm_l + (px0 + 16 * mi + g + t) * SH32 + kb + r;
                ah[mi][0] = arh[0];
                ah[mi][1] = arh[8 * SH32];
                ah[mi][2] = arh[4];
                ah[mi][3] = arh[8 * SH32 + 4];
                al[mi][0] = arl[0];
                al[mi][1] = arl[8 * SH32];
                al[mi][2] = arl[4];
                al[mi][3] = arl[8 * SH32 + 4];
            }
#pragma unroll
            for (int ni = 0; ni < 3; ni++) {
                const uint32_t* brh = wh + (ni * 8 + g) * SH32 + kb + r;
                const uint32_t* brl = wl + (ni * 8 + g) * SH32 + kb + r;
                uint32_t bh[2] = { brh[0], brh[4] };
                uint32_t bl[2] = { brl[0], brl[4] };
#pragma unroll
                for (int mi = 0; mi < 2; mi++) {
                    mma_f16(acc[mi][ni], ah[mi], bh);
                    mma_f16(acc[mi][ni], ah[mi], bl);
                    mma_f16(acc[mi][ni], al[mi], bh);
                }
            }
        }
    };

    for (int rr = 0; rr < 3; rr++) {
        int y = h + rr - 1;
        bool yok = ((unsigned)y < (unsigned)H);

        __syncthreads();

        // stage A row (258-px halo, hi+lo)
        {
            uint4 z4 = make_uint4(0, 0, 0, 0);
            for (int i = tid; i < 2 * OHPX * 8; i += 256) {
                int hf = (i >= OHPX * 8);
                int ii = i - hf * (OHPX * 8);
                int pxs = ii >> 3;         // 0..257 (image w = pxs - 1)
                int c8 = ii & 7;
                int xw = pxs - 1;
                bool ok = yok && ((unsigned)xw < (unsigned)W);
                ptrdiff_t pix = (ptrdiff_t)y * W + xw;
                uint4 v = ok ? (hf ? xl4[pix * (Cin / 8) + c8]
                                   : xh4[pix * (Cin / 8) + c8]) : z4;
                *(uint4*)((hf ? ssm_l : ssm_h) + pxs * SH32 + c8 * 4) = v;
            }
        }
        stageB(3 * rr, 0);
        __syncthreads();

        stageB(3 * rr + 1, 1);
        mmaTap(0, 0);
        __syncthreads();

        stageB(3 * rr + 2, 0);
        mmaTap(1, 1);
        __syncthreads();

        mmaTap(2, 0);
    }

    // epilogue: j = ni*8 + 2r (+1); rows px0+16mi+g, +8; guard j < 18
#pragma unroll
    for (int ni = 0; ni < 3; ni++) {
        int j = ni * 8 + 2 * r;
#pragma unroll
        for (int mi = 0; mi < 2; mi++) {
            int px = px0 + 16 * mi + g;
            if (j < 18) {
                float* ob = g_offs + ((size_t)b * 18 + j) * HW + h * W;
                float bj = b_off[j];
                ob[px]     = acc[mi][ni][0] + bj;
                ob[px + 8] = acc[mi][ni][2] + bj;
            }
            if (j + 1 < 18) {
                float* ob = g_offs + ((size_t)b * 18 + j + 1) * HW + h * W;
                float bj = b_off[j + 1];
                ob[px]     = acc[mi][ni][1] + bj;
                ob[px + 8] = acc[mi][ni][3] + bj;
            }
        }
    }
}

// ---------------------------------------------------------------------------
// Kernel 2: deform — pipelined fp16 MMA (R12 — protected best)
// ---------------------------------------------------------------------------
#define SSM_U32 (MTILE * SH32)            // 4608 u32 = 18432 B per buffer
#define WSM_U32 (OUTC * SH32)             // 2304 u32 =  9216 B per buffer
#define SP_U32  (MTILE * 2)               // 256 u32 = 1024 B per buffer
#define DSMEM_BYTES ((2 * SSM_U32 + 2 * WSM_U32 + 2 * SP_U32) * 4)   // 57344 B

__global__ void __launch_bounds__(256, 4) deform_kernel(
    const float* __restrict__ b_def,
    float* __restrict__ out)
{
    extern __shared__ uint32_t dsm[];
    uint32_t* ssmB[2] = { dsm, dsm + SSM_U32 };
    uint32_t* wsmB[2] = { dsm + 2 * SSM_U32, dsm + 2 * SSM_U32 + WSM_U32 };
    uint32_t* spB[2]  = { dsm + 2 * SSM_U32 + 2 * WSM_U32,
                          dsm + 2 * SSM_U32 + 2 * WSM_U32 + SP_U32 };

    int tid = threadIdx.x;
    int bx = blockIdx.x;
    int wt = (bx & 1) << 7;
    int h = (bx >> 1) & (H - 1);
    int b = bx >> 9;

    const float* offb = g_offs + (size_t)b * 18 * HW + h * W + wt;

    int lane = tid & 31;
    int wid = tid >> 5;
    int warp_m = (wid & 3) << 5;
    int warp_n = (wid >> 2) << 5;
    int r = lane & 3;
    int g = lane >> 2;
    int quarter = lane >> 3;
    int cl8 = lane & 7;
    const uint4* xh4 = (const uint4*)(g_xh + (size_t)b * HW * Cin) + cl8;
    int px0 = wid << 4;

    float acc[2][4][4];
#pragma unroll
    for (int mi = 0; mi < 2; mi++)
#pragma unroll
        for (int ni = 0; ni < 4; ni++)
#pragma unroll
            for (int q = 0; q < 4; q++) acc[mi][ni][q] = 0.f;

    auto computeSp = [&](int kn, uint32_t* spb) {
        if (tid < MTILE) {
            int px = tid;
            float offy = offb[(size_t)(2 * kn) * HW + px];
            float offx = offb[(size_t)(2 * kn + 1) * HW + px];
            float ys = (float)(h + (kn / 3) - 1) + offy;
            float xs = (float)(wt + px + (kn % 3) - 1) + offx;
            float y0f = floorf(ys);
            float x0f = floorf(xs);
            int y0 = (int)y0f;
            int x0 = (int)x0f;
            uint32_t yx = ((uint32_t)(uint16_t)(int16_t)y0)
                        | (((uint32_t)(uint16_t)(int16_t)x0) << 16);
            uint32_t ll = pack_f16x2(ys - y0f, xs - x0f);
            *(uint2*)&spb[px * 2] = make_uint2(yx, ll);
        }
    };

    auto stageW = [&](int k, uint32_t* wsm) {
        const uint4* src = (const uint4*)(g_wh + (size_t)k * OUTC * Cin);
        for (int i = tid; i < OUTC * Cin / 8; i += 256) {
            int o = i >> 3;
            int c8 = i & 7;
            *(uint4*)(wsm + o * SH32 + c8 * 4) = src[i];
        }
    };

    auto gather = [&](uint32_t* ssm, const uint32_t* spb) {
        uint4 z4 = make_uint4(0, 0, 0, 0);
#pragma unroll
        for (int s = 0; s < 4; s++) {
            int px = px0 + 4 * s + quarter;
            uint2 pp = *(const uint2*)&spb[px * 2];
            int y0 = (int)(short)(pp.x & 0xFFFF);
            int x0 = (int)(short)(pp.x >> 16);
            __half2 llh = *(__half2*)&pp.y;
            float ly = __low2float(llh);
            float lx = __high2float(llh);
            float hy = 1.f - ly, hx = 1.f - lx;
            __half2 w00h = __float2half2_rn(hy * hx);
            __half2 w01h = __float2half2_rn(hy * lx);
            __half2 w10h = __float2half2_rn(ly * hx);
            __half2 w11h = __float2half2_rn(ly * lx);
            bool y0k = ((unsigned)y0 < (unsigned)H);
            bool y1k = ((unsigned)(y0 + 1) < (unsigned)H);
            bool x0k = ((unsigned)x0 < (unsigned)W);
            bool x1k = ((unsigned)(x0 + 1) < (unsigned)W);
            const uint4* base = xh4 + ((ptrdiff_t)y0 * W + x0) * (Cin / 8);
            uint4 v00 = (y0k && x0k) ? base[0] : z4;
            uint4 v01 = (y0k && x1k) ? base[Cin / 8] : z4;
            uint4 v10 = (y1k && x0k) ? base[(ptrdiff_t)W * (Cin / 8)] : z4;
            uint4 v11 = (y1k && x1k) ? base[(ptrdiff_t)(W + 1) * (Cin / 8)] : z4;
            uint4 res;
            res.x = bil4(v00.x, v01.x, v10.x, v11.x, w00h, w01h, w10h, w11h);
            res.y = bil4(v00.y, v01.y, v10.y, v11.y, w00h, w01h, w10h, w11h);
            res.z = bil4(v00.z, v01.z, v10.z, v11.z, w00h, w01h, w10h, w11h);
            res.w = bil4(v00.w, v01.w, v10.w, v11.w, w00h, w01h, w10h, w11h);
            *(uint4*)&ssm[px * SH32 + cl8 * 4] = res;
        }
    };

    auto mmaTap = [&](const uint32_t* ssm, const uint32_t* wsm) {
#pragma unroll
        for (int kk = 0; kk < 4; kk++) {
            int kb = kk << 3;
            uint32_t a[2][4];
#pragma unroll
            for (int mi = 0; mi < 2; mi++) {
                const uint32_t* ar = ssm + (warp_m + 16 * mi + g) * SH32 + kb + r;
                a[mi][0] = ar[0];
                a[mi][1] = ar[8 * SH32];
                a[mi][2] = ar[4];
                a[mi][3] = ar[8 * SH32 + 4];
            }
            uint32_t bb[4][2];
#pragma unroll
            for (int ni = 0; ni < 4; ni++) {
                const uint32_t* br = wsm + (warp_n + ni * 8 + g) * SH32 + kb + r;
                bb[ni][0] = br[0];
                bb[ni][1] = br[4];
            }
#pragma unroll
            for (int mi = 0; mi < 2; mi++)
#pragma unroll
                for (int ni = 0; ni < 4; ni++)
                    mma_f16(acc[mi][ni], a[mi], bb[ni]);
        }
    };

    // prologue
    computeSp(0, spB[0]);
    __syncthreads();
    gather(ssmB[0], spB[0]);
    stageW(0, wsmB[0]);
    computeSp(1, spB[1]);
    __syncthreads();

    // pipelined mainloop: one sync per tap
#pragma unroll
    for (int k = 0; k < 9; k++) {
        if (k < 8) {
            gather(ssmB[(k + 1) & 1], spB[(k + 1) & 1]);
            stageW(k + 1, wsmB[(k + 1) & 1]);
            if (k < 7) computeSp(k + 2, spB[k & 1]);
        }
        mmaTap(ssmB[k & 1], wsmB[k & 1]);
        __syncthreads();
    }

    // epilogue: bias + direct stores (NCHW out)
#pragma unroll
    for (int ni = 0; ni < 4; ni++) {
        int o = warp_n + ni * 8 + 2 * r;
        float bo0 = b_def[o];
        float bo1 = b_def[o + 1];
        float* ob0 = out + ((size_t)(b * OUTC + o)) * HW + h * W + wt;
        float* ob1 = ob0 + HW;
#pragma unroll
        for (int mi = 0; mi < 2; mi++) {
            int px = warp_m + mi * 16 + g;
            ob0[px]     = acc[mi][ni][0] + bo0;
            ob1[px]     = acc[mi][ni][1] + bo1;
            ob0[px + 8] = acc[mi][ni][2] + bo0;
            ob1[px + 8] = acc[mi][ni][3] + bo1;
        }
    }
}

// ---------------------------------------------------------------------------
extern "C" void kernel_launch(void* const* d_in, const int* in_sizes, int n_in,
                              void* d_out, int out_size)
{
    const float* x     = (const float*)d_in[0];
    const float* w_off = (const float*)d_in[1];
    const float* b_off = (const float*)d_in[2];
    const float* w_def = (const float*)d_in[3];
    const float* b_def = (const float*)d_in[4];
    float* out = (float*)d_out;

    cudaFuncSetAttribute(deform_kernel,
                         cudaFuncAttributeMaxDynamicSharedMemorySize, DSMEM_BYTES);
    cudaFuncSetAttribute(offsets_kernel,
                         cudaFuncAttributeMaxDynamicSharedMemorySize, OFF_DSMEM);

    prep_wdef_kernel<<<(9 * OUTC * Cin + 255) / 256, 256>>>(w_def);
    prep_woff_kernel<<<(9 * OJ * Cin + 255) / 256, 256>>>(w_off);
    transpose_x_kernel<<<Bsz * H * (W / 32), 256>>>(x);
    offsets_kernel<<<Bsz * H, 256, OFF_DSMEM>>>(b_off);
    deform_kernel<<<Bsz * H * (W / MTILE), 256, DSMEM_BYTES>>>(b_def, out);
}

// round 15
// speedup vs baseline: 1.0315x; 1.0315x over previous
#include <cuda_runtime.h>
#include <cuda_fp16.h>
#include <cstdint>

#define Bsz 4
#define Cin 64
#define OUTC 64
#define H 256
#define W 256
#define HW (H*W)

#define MTILE 128          // pixels per CTA (half row)
#define SH 72              // stride in halves (64 + 8 pad) -> conflict-free
#define SH32 (SH/2)        // = 36 u32 per row
#define ROWB (SH32 * 4)    // = 144 bytes per row

#define OJ 24              // offset channels 18 padded to 24
#define HPX 130            // offsets A-halo pixels: -1 .. 128

// Scratch (device globals — no allocation allowed)
__device__ float g_offs[(size_t)Bsz * 18 * HW];        // offset conv output (fp32-accurate)
__device__ __half g_wh[9 * OUTC * Cin];                // w_def -> [k][o][c] fp16
__device__ __half g_xh[(size_t)Bsz * HW * Cin];        // x NHWC fp16 hi (33.5MB)
__device__ __half g_xl[(size_t)Bsz * HW * Cin];        // x NHWC fp16 lo (33.5MB)
__device__ __half g_wo_hi[9 * OJ * Cin];               // w_off split hi [k][j][c]
__device__ __half g_wo_lo[9 * OJ * Cin];               // w_off split lo [k][j][c]

// ---------------------------------------------------------------------------
// helpers
// ---------------------------------------------------------------------------
__device__ __forceinline__ void mma_f16(float* d, const uint32_t* a, const uint32_t* b) {
    asm volatile(
        "mma.sync.aligned.m16n8k16.row.col.f32.f16.f16.f32 "
        "{%0,%1,%2,%3}, {%4,%5,%6,%7}, {%8,%9}, {%0,%1,%2,%3};"
        : "+f"(d[0]), "+f"(d[1]), "+f"(d[2]), "+f"(d[3])
        : "r"(a[0]), "r"(a[1]), "r"(a[2]), "r"(a[3]),
          "r"(b[0]), "r"(b[1]));
}

__device__ __forceinline__ void ldsm_x4(uint32_t& r0, uint32_t& r1,
                                        uint32_t& r2, uint32_t& r3, uint32_t addr) {
    asm volatile("ldmatrix.sync.aligned.m8n8.x4.shared.b16 {%0,%1,%2,%3}, [%4];"
        : "=r"(r0), "=r"(r1), "=r"(r2), "=r"(r3) : "r"(addr));
}

__device__ __forceinline__ uint32_t smem_u32(const void* p) {
    uint32_t a;
    asm("{ .reg .u64 t; cvta.to.shared.u64 t, %1; cvt.u32.u64 %0, t; }"
        : "=r"(a) : "l"(p));
    return a;
}

__device__ __forceinline__ uint32_t pack_f16x2(float lo, float hi) {
    uint32_t r;
    asm("cvt.rn.f16x2.f32 %0, %1, %2;" : "=r"(r) : "f"(hi), "f"(lo));
    return r;
}

__device__ __forceinline__ uint32_t bil4(uint32_t a, uint32_t b, uint32_t c, uint32_t d,
                                         __half2 w00, __half2 w01, __half2 w10, __half2 w11) {
    __half2 r = __hmul2(*(__half2*)&a, w00);
    r = __hfma2(*(__half2*)&b, w01, r);
    r = __hfma2(*(__half2*)&c, w10, r);
    r = __hfma2(*(__half2*)&d, w11, r);
    return *(uint32_t*)&r;
}

// ---------------------------------------------------------------------------
// Kernel 0a: w_def [o][c][ki][kj] -> g_wh[k][o][c] (fp16)
// ---------------------------------------------------------------------------
__global__ void prep_wdef_kernel(const float* __restrict__ w_def) {
    int idx = blockIdx.x * 256 + threadIdx.x;
    if (idx >= 9 * OUTC * Cin) return;
    int k = idx / (OUTC * Cin);
    int rem = idx - k * (OUTC * Cin);
    int o = rem / Cin;
    int c = rem - o * Cin;
    g_wh[idx] = __float2half_rn(w_def[(o * Cin + c) * 9 + k]);
}

// ---------------------------------------------------------------------------
// Kernel 0b: w_off [j][c][ki][kj] -> g_wo_{hi,lo}[k][j][c] fp16 split
// ---------------------------------------------------------------------------
__global__ void prep_woff_kernel(const float* __restrict__ w_off) {
    int idx = blockIdx.x * 256 + threadIdx.x;      // 13824
    if (idx >= 9 * OJ * Cin) return;
    int k = idx / (OJ * Cin);
    int rem = idx - k * (OJ * Cin);
    int j = rem / Cin;
    int c = rem - j * Cin;
    float v = (j < 18) ? w_off[((size_t)j * Cin + c) * 9 + k] : 0.f;
    __half hi = __float2half_rn(v);
    float lo = v - __half2float(hi);
    g_wo_hi[idx] = hi;
    g_wo_lo[idx] = __float2half_rn(lo);
}

// ---------------------------------------------------------------------------
// Kernel 0c: transpose x NCHW -> NHWC fp16 split (g_xh + g_xl)
// ---------------------------------------------------------------------------
__global__ void __launch_bounds__(256) transpose_x_kernel(const float* __restrict__ x) {
    __shared__ float t[Cin][33];
    int tid = threadIdx.x;
    int bx = blockIdx.x;
    int wt = (bx & 7) << 5;
    int h = (bx >> 3) & (H - 1);
    int b = bx >> 11;

    const float* xb = x + (size_t)b * Cin * HW + h * W + wt;
#pragma unroll
    for (int it = 0; it < 8; it++) {
        int c = it * 8 + (tid >> 5);
        int w = tid & 31;
        t[c][w] = xb[(size_t)c * HW + w];
    }
    __syncthreads();
    size_t base = ((size_t)(b * H + h) * W + wt) * Cin;
    uint32_t* xh = (uint32_t*)(g_xh + base);
    uint32_t* xl = (uint32_t*)(g_xl + base);
#pragma unroll
    for (int it = 0; it < 4; it++) {
        int w = it * 8 + (tid >> 5);
        int c2 = tid & 31;
        float a0 = t[2 * c2][w];
        float a1 = t[2 * c2 + 1][w];
        __half h0 = __float2half_rn(a0);
        __half h1 = __float2half_rn(a1);
        __half2 hp = __halves2half2(h0, h1);
        float l0 = a0 - __half2float(h0);
        float l1 = a1 - __half2float(h1);
        xh[w * (Cin / 2) + c2] = *(uint32_t*)&hp;
        xl[w * (Cin / 2) + c2] = pack_f16x2(l0, l1);
    }
}

// ---------------------------------------------------------------------------
// Kernel 1: offsets conv, fp16 split MMA, row-reuse (R11 exact — proven 89.6us)
// ---------------------------------------------------------------------------
#define OFF_SSM_U32 (HPX * SH32)                    // 4680 per half
#define OFF_WTAP_U32 (2 * OJ * SH32)                // 1728 per tap (hi+lo)
#define OFF_DSMEM ((2 * OFF_SSM_U32 + 2 * OFF_WTAP_U32) * 4)   // 51264 B

__global__ void __launch_bounds__(256, 4) offsets_kernel(
    const float* __restrict__ b_off)
{
    extern __shared__ uint32_t dsm[];
    uint32_t* ssm_h = dsm;                              // [130 px][c] hi
    uint32_t* ssm_l = ssm_h + OFF_SSM_U32;              // lo
    uint32_t* wbuf = ssm_l + OFF_SSM_U32;               // 2 x (hi 864 | lo 864)

    int tid = threadIdx.x;
    int bx = blockIdx.x;
    int wt = (bx & 1) << 7;
    int h = (bx >> 1) & (H - 1);
    int b = bx >> 9;

    int lane = tid & 31;
    int wid = tid >> 5;
    int r = lane & 3;
    int g = lane >> 2;
    int px0 = wid << 4;

    float acc[3][4];
#pragma unroll
    for (int ni = 0; ni < 3; ni++)
#pragma unroll
        for (int q = 0; q < 4; q++) acc[ni][q] = 0.f;

    const uint4* xh4 = (const uint4*)(g_xh + (size_t)b * HW * Cin);
    const uint4* xl4 = (const uint4*)(g_xl + (size_t)b * HW * Cin);

    auto stageB = [&](int k, int buf) {
        uint32_t* wh = wbuf + buf * OFF_WTAP_U32;
        uint32_t* wl = wh + OJ * SH32;
        const uint4* sh = (const uint4*)(g_wo_hi + (size_t)k * OJ * Cin);
        const uint4* sl = (const uint4*)(g_wo_lo + (size_t)k * OJ * Cin);
        for (int i = tid; i < 2 * OJ * Cin / 8; i += 256) {
            int hf = (i >= OJ * Cin / 8);
            int ii = i - hf * (OJ * Cin / 8);
            int j = ii >> 3;
            int c8 = ii & 7;
            uint4 v = hf ? sl[ii] : sh[ii];
            *(uint4*)((hf ? wl : wh) + j * SH32 + c8 * 4) = v;
        }
    };

    auto mmaTap = [&](int t, int buf) {
        uint32_t* wh = wbuf + buf * OFF_WTAP_U32;
        uint32_t* wl = wh + OJ * SH32;
#pragma unroll
        for (int kk = 0; kk < 4; kk++) {
            int kb = kk << 3;
            uint32_t ah[4], al[4];
            const uint32_t* arh = ssm_h + (px0 + g + t) * SH32 + kb + r;
            const uint32_t* arl = ssm_l + (px0 + g + t) * SH32 + kb + r;
            ah[0] = arh[0];
            ah[1] = arh[8 * SH32];
            ah[2] = arh[4];
            ah[3] = arh[8 * SH32 + 4];
            al[0] = arl[0];
            al[1] = arl[8 * SH32];
            al[2] = arl[4];
            al[3] = arl[8 * SH32 + 4];
#pragma unroll
            for (int ni = 0; ni < 3; ni++) {
                const uint32_t* brh = wh + (ni * 8 + g) * SH32 + kb + r;
                const uint32_t* brl = wl + (ni * 8 + g) * SH32 + kb + r;
                uint32_t bh[2] = { brh[0], brh[4] };
                uint32_t bl[2] = { brl[0], brl[4] };
                mma_f16(acc[ni], ah, bh);
                mma_f16(acc[ni], ah, bl);
                mma_f16(acc[ni], al, bh);
            }
        }
    };

    for (int rr = 0; rr < 3; rr++) {
        int y = h + rr - 1;
        bool yok = ((unsigned)y < (unsigned)H);

        __syncthreads();

        {
            uint4 z4 = make_uint4(0, 0, 0, 0);
            for (int i = tid; i < 2 * HPX * 8; i += 256) {
                int hf = (i >= HPX * 8);
                int ii = i - hf * (HPX * 8);
                int pxs = ii >> 3;
                int c8 = ii & 7;
                int xw = wt + pxs - 1;
                bool ok = yok && ((unsigned)xw < (unsigned)W);
                ptrdiff_t pix = (ptrdiff_t)y * W + xw;
                uint4 v = ok ? (hf ? xl4[pix * (Cin / 8) + c8]
                                   : xh4[pix * (Cin / 8) + c8]) : z4;
                *(uint4*)((hf ? ssm_l : ssm_h) + pxs * SH32 + c8 * 4) = v;
            }
        }
        stageB(3 * rr, 0);
        __syncthreads();

        stageB(3 * rr + 1, 1);
        mmaTap(0, 0);
        __syncthreads();

        stageB(3 * rr + 2, 0);
        mmaTap(1, 1);
        __syncthreads();

        mmaTap(2, 0);
    }

#pragma unroll
    for (int ni = 0; ni < 3; ni++) {
        int j = ni * 8 + 2 * r;
        if (j < 18) {
            float* ob = g_offs + ((size_t)b * 18 + j) * HW + h * W + wt;
            float bj = b_off[j];
            ob[px0 + g]     = acc[ni][0] + bj;
            ob[px0 + g + 8] = acc[ni][2] + bj;
        }
        if (j + 1 < 18) {
            float* ob = g_offs + ((size_t)b * 18 + j + 1) * HW + h * W + wt;
            float bj = b_off[j + 1];
            ob[px0 + g]     = acc[ni][1] + bj;
            ob[px0 + g + 8] = acc[ni][3] + bj;
        }
    }
}

// ---------------------------------------------------------------------------
// Kernel 2: deform — pipelined fp16 MMA (R12 structure) with LDSM fragment
// loads: 4x ldmatrix.x4 per kk replaces 16 scalar LDS (bit-identical frags).
// ---------------------------------------------------------------------------
#define SSM_U32 (MTILE * SH32)            // 4608 u32 = 18432 B per buffer
#define WSM_U32 (OUTC * SH32)             // 2304 u32 =  9216 B per buffer
#define SP_U32  (MTILE * 2)               // 256 u32 = 1024 B per buffer
#define DSMEM_BYTES ((2 * SSM_U32 + 2 * WSM_U32 + 2 * SP_U32) * 4)   // 57344 B

__global__ void __launch_bounds__(256, 4) deform_kernel(
    const float* __restrict__ b_def,
    float* __restrict__ out)
{
    extern __shared__ uint32_t dsm[];
    uint32_t* ssmB[2] = { dsm, dsm + SSM_U32 };
    uint32_t* wsmB[2] = { dsm + 2 * SSM_U32, dsm + 2 * SSM_U32 + WSM_U32 };
    uint32_t* spB[2]  = { dsm + 2 * SSM_U32 + 2 * WSM_U32,
                          dsm + 2 * SSM_U32 + 2 * WSM_U32 + SP_U32 };

    int tid = threadIdx.x;
    int bx = blockIdx.x;
    int wt = (bx & 1) << 7;
    int h = (bx >> 1) & (H - 1);
    int b = bx >> 9;

    const float* offb = g_offs + (size_t)b * 18 * HW + h * W + wt;

    int lane = tid & 31;
    int wid = tid >> 5;
    int warp_m = (wid & 3) << 5;
    int warp_n = (wid >> 2) << 5;
    int r = lane & 3;
    int g = lane >> 2;
    int quarter = lane >> 3;
    int cl8 = lane & 7;
    const uint4* xh4 = (const uint4*)(g_xh + (size_t)b * HW * Cin) + cl8;
    int px0 = wid << 4;

    float acc[2][4][4];
#pragma unroll
    for (int mi = 0; mi < 2; mi++)
#pragma unroll
        for (int ni = 0; ni < 4; ni++)
#pragma unroll
            for (int q = 0; q < 4; q++) acc[mi][ni][q] = 0.f;

    // per-lane ldmatrix address offsets (bytes, within a buffer)
    // A: row = warp_m + 16*mi + (lane&15); col16 = (lane>>4)*16
    uint32_t aoff = (uint32_t)(warp_m + (lane & 15)) * ROWB + ((lane >> 4) << 4);
    // B: row = warp_n + (lane>>4)*8 + (lane&7); col16 = ((lane>>3)&1)*16
    uint32_t boff = (uint32_t)(warp_n + ((lane >> 4) << 3) + (lane & 7)) * ROWB
                  + (((lane >> 3) & 1) << 4);

    auto computeSp = [&](int kn, uint32_t* spb) {
        if (tid < MTILE) {
            int px = tid;
            float offy = offb[(size_t)(2 * kn) * HW + px];
            float offx = offb[(size_t)(2 * kn + 1) * HW + px];
            float ys = (float)(h + (kn / 3) - 1) + offy;
            float xs = (float)(wt + px + (kn % 3) - 1) + offx;
            float y0f = floorf(ys);
            float x0f = floorf(xs);
            int y0 = (int)y0f;
            int x0 = (int)x0f;
            uint32_t yx = ((uint32_t)(uint16_t)(int16_t)y0)
                        | (((uint32_t)(uint16_t)(int16_t)x0) << 16);
            uint32_t ll = pack_f16x2(ys - y0f, xs - x0f);
            *(uint2*)&spb[px * 2] = make_uint2(yx, ll);
        }
    };

    auto stageW = [&](int k, uint32_t* wsm) {
        const uint4* src = (const uint4*)(g_wh + (size_t)k * OUTC * Cin);
        for (int i = tid; i < OUTC * Cin / 8; i += 256) {
            int o = i >> 3;
            int c8 = i & 7;
            *(uint4*)(wsm + o * SH32 + c8 * 4) = src[i];
        }
    };

    auto gather = [&](uint32_t* ssm, const uint32_t* spb) {
        uint4 z4 = make_uint4(0, 0, 0, 0);
#pragma unroll
        for (int s = 0; s < 4; s++) {
            int px = px0 + 4 * s + quarter;
            uint2 pp = *(const uint2*)&spb[px * 2];
            int y0 = (int)(short)(pp.x & 0xFFFF);
            int x0 = (int)(short)(pp.x >> 16);
            __half2 llh = *(__half2*)&pp.y;
            float ly = __low2float(llh);
            float lx = __high2float(llh);
            float hy = 1.f - ly, hx = 1.f - lx;
            __half2 w00h = __float2half2_rn(hy * hx);
            __half2 w01h = __float2half2_rn(hy * lx);
            __half2 w10h = __float2half2_rn(ly * hx);
            __half2 w11h = __float2half2_rn(ly * lx);
            bool y0k = ((unsigned)y0 < (unsigned)H);
            bool y1k = ((unsigned)(y0 + 1) < (unsigned)H);
            bool x0k = ((unsigned)x0 < (unsigned)W);
            bool x1k = ((unsigned)(x0 + 1) < (unsigned)W);
            const uint4* base = xh4 + ((ptrdiff_t)y0 * W + x0) * (Cin / 8);
            uint4 v00 = (y0k && x0k) ? base[0] : z4;
            uint4 v01 = (y0k && x1k) ? base[Cin / 8] : z4;
            uint4 v10 = (y1k && x0k) ? base[(ptrdiff_t)W * (Cin / 8)] : z4;
            uint4 v11 = (y1k && x1k) ? base[(ptrdiff_t)(W + 1) * (Cin / 8)] : z4;
            uint4 res;
            res.x = bil4(v00.x, v01.x, v10.x, v11.x, w00h, w01h, w10h, w11h);
            res.y = bil4(v00.y, v01.y, v10.y, v11.y, w00h, w01h, w10h, w11h);
            res.z = bil4(v00.z, v01.z, v10.z, v11.z, w00h, w01h, w10h, w11h);
            res.w = bil4(v00.w, v01.w, v10.w, v11.w, w00h, w01h, w10h, w11h);
            *(uint4*)&ssm[px * SH32 + cl8 * 4] = res;
        }
    };

    auto mmaTap = [&](const uint32_t* ssm, const uint32_t* wsm) {
        uint32_t abase = smem_u32(ssm) + aoff;
        uint32_t bbase = smem_u32(wsm) + boff;
#pragma unroll
        for (int kk = 0; kk < 4; kk++) {
            uint32_t koff = (uint32_t)kk << 5;     // 32 bytes = 16 halves
            uint32_t a[2][4];
            ldsm_x4(a[0][0], a[0][1], a[0][2], a[0][3], abase + koff);
            ldsm_x4(a[1][0], a[1][1], a[1][2], a[1][3], abase + 16 * ROWB + koff);
            uint32_t bb[4][2];
            ldsm_x4(bb[0][0], bb[0][1], bb[1][0], bb[1][1], bbase + koff);
            ldsm_x4(bb[2][0], bb[2][1], bb[3][0], bb[3][1], bbase + 16 * ROWB + koff);
#pragma unroll
            for (int mi = 0; mi < 2; mi++)
#pragma unroll
                for (int ni = 0; ni < 4; ni++)
                    mma_f16(acc[mi][ni], a[mi], bb[ni]);
        }
    };

    // prologue
    computeSp(0, spB[0]);
    __syncthreads();
    gather(ssmB[0], spB[0]);
    stageW(0, wsmB[0]);
    computeSp(1, spB[1]);
    __syncthreads();

    // pipelined mainloop: one sync per tap
#pragma unroll
    for (int k = 0; k < 9; k++) {
        if (k < 8) {
            gather(ssmB[(k + 1) & 1], spB[(k + 1) & 1]);
            stageW(k + 1, wsmB[(k + 1) & 1]);
            if (k < 7) computeSp(k + 2, spB[k & 1]);
        }
        mmaTap(ssmB[k & 1], wsmB[k & 1]);
        __syncthreads();
    }

    // epilogue: bias + direct stores (NCHW out)
#pragma unroll
    for (int ni = 0; ni < 4; ni++) {
        int o = warp_n + ni * 8 + 2 * r;
        float bo0 = b_def[o];
        float bo1 = b_def[o + 1];
        float* ob0 = out + ((size_t)(b * OUTC + o)) * HW + h * W + wt;
        float* ob1 = ob0 + HW;
#pragma unroll
        for (int mi = 0; mi < 2; mi++) {
            int px = warp_m + mi * 16 + g;
            ob0[px]     = acc[mi][ni][0] + bo0;
            ob1[px]     = acc[mi][ni][1] + bo1;
            ob0[px + 8] = acc[mi][ni][2] + bo0;
            ob1[px + 8] = acc[mi][ni][3] + bo1;
        }
    }
}

// ---------------------------------------------------------------------------
extern "C" void kernel_launch(void* const* d_in, const int* in_sizes, int n_in,
                              void* d_out, int out_size)
{
    const float* x     = (const float*)d_in[0];
    const float* w_off = (const float*)d_in[1];
    const float* b_off = (const float*)d_in[2];
    const float* w_def = (const float*)d_in[3];
    const float* b_def = (const float*)d_in[4];
    float* out = (float*)d_out;

    cudaFuncSetAttribute(deform_kernel,
                         cudaFuncAttributeMaxDynamicSharedMemorySize, DSMEM_BYTES);
    cudaFuncSetAttribute(offsets_kernel,
                         cudaFuncAttributeMaxDynamicSharedMemorySize, OFF_DSMEM);

    prep_wdef_kernel<<<(9 * OUTC * Cin + 255) / 256, 256>>>(w_def);
    prep_woff_kernel<<<(9 * OJ * Cin + 255) / 256, 256>>>(w_off);
    transpose_x_kernel<<<Bsz * H * (W / 32), 256>>>(x);
    offsets_kernel<<<Bsz * H * (W / MTILE), 256, OFF_DSMEM>>>(b_off);
    deform_kernel<<<Bsz * H * (W / MTILE), 256, DSMEM_BYTES>>>(b_def, out);
}

// round 16
// speedup vs baseline: 1.1977x; 1.1611x over previous
#include <cuda_runtime.h>
#include <cuda_fp16.h>
#include <cstdint>

#define Bsz 4
#define Cin 64
#define OUTC 64
#define H 256
#define W 256
#define HW (H*W)

#define MTILE 128          // pixels per CTA (half row)
#define SH 72              // stride in halves (64 + 8 pad) -> conflict-free
#define SH32 (SH/2)        // = 36 u32 per row

#define OJ 24              // offset channels 18 padded to 24
#define HPX 130            // offsets A-halo pixels: -1 .. 128

// Scratch (device globals — no allocation allowed)
__device__ float g_offs[(size_t)Bsz * 18 * HW];        // offset conv output (fp32-accurate)
__device__ uint2 g_wfrag[9 * 8 * 4 * 32];              // w_def fragment-ordered [k][nt][kk][lane]
__device__ __half g_xh[(size_t)Bsz * HW * Cin];        // x NHWC fp16 hi (33.5MB)
__device__ __half g_xl[(size_t)Bsz * HW * Cin];        // x NHWC fp16 lo (33.5MB)
__device__ __half g_wo_hi[9 * OJ * Cin];               // w_off split hi [k][j][c]
__device__ __half g_wo_lo[9 * OJ * Cin];               // w_off split lo [k][j][c]

// ---------------------------------------------------------------------------
// helpers
// ---------------------------------------------------------------------------
__device__ __forceinline__ void mma_f16(float* d, const uint32_t* a, const uint32_t* b) {
    asm volatile(
        "mma.sync.aligned.m16n8k16.row.col.f32.f16.f16.f32 "
        "{%0,%1,%2,%3}, {%4,%5,%6,%7}, {%8,%9}, {%0,%1,%2,%3};"
        : "+f"(d[0]), "+f"(d[1]), "+f"(d[2]), "+f"(d[3])
        : "r"(a[0]), "r"(a[1]), "r"(a[2]), "r"(a[3]),
          "r"(b[0]), "r"(b[1]));
}

__device__ __forceinline__ uint32_t pack_f16x2(float lo, float hi) {
    uint32_t r;
    asm("cvt.rn.f16x2.f32 %0, %1, %2;" : "=r"(r) : "f"(hi), "f"(lo));
    return r;
}

__device__ __forceinline__ uint32_t bil4(uint32_t a, uint32_t b, uint32_t c, uint32_t d,
                                         __half2 w00, __half2 w01, __half2 w10, __half2 w11) {
    __half2 r = __hmul2(*(__half2*)&a, w00);
    r = __hfma2(*(__half2*)&b, w01, r);
    r = __hfma2(*(__half2*)&c, w10, r);
    r = __hfma2(*(__half2*)&d, w11, r);
    return *(uint32_t*)&r;
}

// ---------------------------------------------------------------------------
// Kernel 0a (fused preps): g_wfrag from w_def + g_wo_{hi,lo} from w_off
// ---------------------------------------------------------------------------
__global__ void prep_fused_kernel(const float* __restrict__ w_def,
                                  const float* __restrict__ w_off) {
    int idx = blockIdx.x * 256 + threadIdx.x;
    if (idx < 9 * 8 * 4 * 32) {
        // fragment-ordered w_def: [k][nt][kk][lane] -> uint2
        int lane = idx & 31;
        int kk = (idx >> 5) & 3;
        int nt = (idx >> 7) & 7;
        int k = idx >> 10;
        int o = nt * 8 + (lane >> 2);
        int r = lane & 3;
        int c0 = kk * 16 + 2 * r;          // q=0 halves c0, c0+1
        int c1 = c0 + 8;                   // q=1 halves c1, c1+1
        uint2 v;
        {
            __half lo = __float2half_rn(w_def[(o * Cin + c0) * 9 + k]);
            __half hi = __float2half_rn(w_def[(o * Cin + c0 + 1) * 9 + k]);
            __half2 p = __halves2half2(lo, hi);
            v.x = *(uint32_t*)&p;
        }
        {
            __half lo = __float2half_rn(w_def[(o * Cin + c1) * 9 + k]);
            __half hi = __float2half_rn(w_def[(o * Cin + c1 + 1) * 9 + k]);
            __half2 p = __halves2half2(lo, hi);
            v.y = *(uint32_t*)&p;
        }
        g_wfrag[idx] = v;
        return;
    }
    idx -= 9 * 8 * 4 * 32;
    if (idx >= 9 * OJ * Cin) return;
    int k = idx / (OJ * Cin);
    int rem = idx - k * (OJ * Cin);
    int j = rem / Cin;
    int c = rem - j * Cin;
    float v = (j < 18) ? w_off[((size_t)j * Cin + c) * 9 + k] : 0.f;
    __half hi = __float2half_rn(v);
    float lo = v - __half2float(hi);
    g_wo_hi[idx] = hi;
    g_wo_lo[idx] = __float2half_rn(lo);
}

// ---------------------------------------------------------------------------
// Kernel 0b: transpose x NCHW -> NHWC fp16 split (g_xh + g_xl)
// ---------------------------------------------------------------------------
__global__ void __launch_bounds__(256) transpose_x_kernel(const float* __restrict__ x) {
    __shared__ float t[Cin][33];
    int tid = threadIdx.x;
    int bx = blockIdx.x;
    int wt = (bx & 7) << 5;
    int h = (bx >> 3) & (H - 1);
    int b = bx >> 11;

    const float* xb = x + (size_t)b * Cin * HW + h * W + wt;
#pragma unroll
    for (int it = 0; it < 8; it++) {
        int c = it * 8 + (tid >> 5);
        int w = tid & 31;
        t[c][w] = xb[(size_t)c * HW + w];
    }
    __syncthreads();
    size_t base = ((size_t)(b * H + h) * W + wt) * Cin;
    uint32_t* xh = (uint32_t*)(g_xh + base);
    uint32_t* xl = (uint32_t*)(g_xl + base);
#pragma unroll
    for (int it = 0; it < 4; it++) {
        int w = it * 8 + (tid >> 5);
        int c2 = tid & 31;
        float a0 = t[2 * c2][w];
        float a1 = t[2 * c2 + 1][w];
        __half h0 = __float2half_rn(a0);
        __half h1 = __float2half_rn(a1);
        __half2 hp = __halves2half2(h0, h1);
        float l0 = a0 - __half2float(h0);
        float l1 = a1 - __half2float(h1);
        xh[w * (Cin / 2) + c2] = *(uint32_t*)&hp;
        xl[w * (Cin / 2) + c2] = pack_f16x2(l0, l1);
    }
}

// ---------------------------------------------------------------------------
// Kernel 1: offsets conv, fp16 split MMA, row-reuse (R11 exact — proven)
// ---------------------------------------------------------------------------
#define OFF_SSM_U32 (HPX * SH32)                    // 4680 per half
#define OFF_WTAP_U32 (2 * OJ * SH32)                // 1728 per tap (hi+lo)
#define OFF_DSMEM ((2 * OFF_SSM_U32 + 2 * OFF_WTAP_U32) * 4)   // 51264 B

__global__ void __launch_bounds__(256, 4) offsets_kernel(
    const float* __restrict__ b_off)
{
    extern __shared__ uint32_t dsm[];
    uint32_t* ssm_h = dsm;                              // [130 px][c] hi
    uint32_t* ssm_l = ssm_h + OFF_SSM_U32;              // lo
    uint32_t* wbuf = ssm_l + OFF_SSM_U32;               // 2 x (hi 864 | lo 864)

    int tid = threadIdx.x;
    int bx = blockIdx.x;
    int wt = (bx & 1) << 7;
    int h = (bx >> 1) & (H - 1);
    int b = bx >> 9;

    int lane = tid & 31;
    int wid = tid >> 5;
    int r = lane & 3;
    int g = lane >> 2;
    int px0 = wid << 4;

    float acc[3][4];
#pragma unroll
    for (int ni = 0; ni < 3; ni++)
#pragma unroll
        for (int q = 0; q < 4; q++) acc[ni][q] = 0.f;

    const uint4* xh4 = (const uint4*)(g_xh + (size_t)b * HW * Cin);
    const uint4* xl4 = (const uint4*)(g_xl + (size_t)b * HW * Cin);

    auto stageB = [&](int k, int buf) {
        uint32_t* wh = wbuf + buf * OFF_WTAP_U32;
        uint32_t* wl = wh + OJ * SH32;
        const uint4* sh = (const uint4*)(g_wo_hi + (size_t)k * OJ * Cin);
        const uint4* sl = (const uint4*)(g_wo_lo + (size_t)k * OJ * Cin);
        for (int i = tid; i < 2 * OJ * Cin / 8; i += 256) {
            int hf = (i >= OJ * Cin / 8);
            int ii = i - hf * (OJ * Cin / 8);
            int j = ii >> 3;
            int c8 = ii & 7;
            uint4 v = hf ? sl[ii] : sh[ii];
            *(uint4*)((hf ? wl : wh) + j * SH32 + c8 * 4) = v;
        }
    };

    auto mmaTap = [&](int t, int buf) {
        uint32_t* wh = wbuf + buf * OFF_WTAP_U32;
        uint32_t* wl = wh + OJ * SH32;
#pragma unroll
        for (int kk = 0; kk < 4; kk++) {
            int kb = kk << 3;
            uint32_t ah[4], al[4];
            const uint32_t* arh = ssm_h + (px0 + g + t) * SH32 + kb + r;
            const uint32_t* arl = ssm_l + (px0 + g + t) * SH32 + kb + r;
            ah[0] = arh[0];
            ah[1] = arh[8 * SH32];
            ah[2] = arh[4];
            ah[3] = arh[8 * SH32 + 4];
            al[0] = arl[0];
            al[1] = arl[8 * SH32];
            al[2] = arl[4];
            al[3] = arl[8 * SH32 + 4];
#pragma unroll
            for (int ni = 0; ni < 3; ni++) {
                const uint32_t* brh = wh + (ni * 8 + g) * SH32 + kb + r;
                const uint32_t* brl = wl + (ni * 8 + g) * SH32 + kb + r;
                uint32_t bh[2] = { brh[0], brh[4] };
                uint32_t bl[2] = { brl[0], brl[4] };
                mma_f16(acc[ni], ah, bh);
                mma_f16(acc[ni], ah, bl);
                mma_f16(acc[ni], al, bh);
            }
        }
    };

    for (int rr = 0; rr < 3; rr++) {
        int y = h + rr - 1;
        bool yok = ((unsigned)y < (unsigned)H);

        __syncthreads();

        {
            uint4 z4 = make_uint4(0, 0, 0, 0);
            for (int i = tid; i < 2 * HPX * 8; i += 256) {
                int hf = (i >= HPX * 8);
                int ii = i - hf * (HPX * 8);
                int pxs = ii >> 3;
                int c8 = ii & 7;
                int xw = wt + pxs - 1;
                bool ok = yok && ((unsigned)xw < (unsigned)W);
                ptrdiff_t pix = (ptrdiff_t)y * W + xw;
                uint4 v = ok ? (hf ? xl4[pix * (Cin / 8) + c8]
                                   : xh4[pix * (Cin / 8) + c8]) : z4;
                *(uint4*)((hf ? ssm_l : ssm_h) + pxs * SH32 + c8 * 4) = v;
            }
        }
        stageB(3 * rr, 0);
        __syncthreads();

        stageB(3 * rr + 1, 1);
        mmaTap(0, 0);
        __syncthreads();

        stageB(3 * rr + 2, 0);
        mmaTap(1, 1);
        __syncthreads();

        mmaTap(2, 0);
    }

#pragma unroll
    for (int ni = 0; ni < 3; ni++) {
        int j = ni * 8 + 2 * r;
        if (j < 18) {
            float* ob = g_offs + ((size_t)b * 18 + j) * HW + h * W + wt;
            float bj = b_off[j];
            ob[px0 + g]     = acc[ni][0] + bj;
            ob[px0 + g + 8] = acc[ni][2] + bj;
        }
        if (j + 1 < 18) {
            float* ob = g_offs + ((size_t)b * 18 + j + 1) * HW + h * W + wt;
            float bj = b_off[j + 1];
            ob[px0 + g]     = acc[ni][1] + bj;
            ob[px0 + g + 8] = acc[ni][3] + bj;
        }
    }
}

// ---------------------------------------------------------------------------
// Kernel 2: deform — R12 pipelined structure; B frags loaded directly from
// fragment-ordered global (no wsm, no stageW). smem 38.9KB.
// ---------------------------------------------------------------------------
#define SSM_U32 (MTILE * SH32)            // 4608 u32 = 18432 B per buffer
#define SP_U32  (MTILE * 2)               // 256 u32 = 1024 B per buffer
#define DSMEM_BYTES ((2 * SSM_U32 + 2 * SP_U32) * 4)   // 38912 B

__global__ void __launch_bounds__(256, 4) deform_kernel(
    const float* __restrict__ b_def,
    float* __restrict__ out)
{
    extern __shared__ uint32_t dsm[];
    uint32_t* ssmB[2] = { dsm, dsm + SSM_U32 };
    uint32_t* spB[2]  = { dsm + 2 * SSM_U32, dsm + 2 * SSM_U32 + SP_U32 };

    int tid = threadIdx.x;
    int bx = blockIdx.x;
    int wt = (bx & 1) << 7;
    int h = (bx >> 1) & (H - 1);
    int b = bx >> 9;

    const float* offb = g_offs + (size_t)b * 18 * HW + h * W + wt;

    int lane = tid & 31;
    int wid = tid >> 5;
    int warp_m = (wid & 3) << 5;
    int warp_n = (wid >> 2) << 5;
    int r = lane & 3;
    int g = lane >> 2;
    int quarter = lane >> 3;
    int cl8 = lane & 7;
    const uint4* xh4 = (const uint4*)(g_xh + (size_t)b * HW * Cin) + cl8;
    int px0 = wid << 4;
    int nb = warp_n >> 3;              // n-tile base: 0 or 4
    const uint2* wfb = g_wfrag + lane;

    float acc[2][4][4];
#pragma unroll
    for (int mi = 0; mi < 2; mi++)
#pragma unroll
        for (int ni = 0; ni < 4; ni++)
#pragma unroll
            for (int q = 0; q < 4; q++) acc[mi][ni][q] = 0.f;

    auto computeSp = [&](int kn, uint32_t* spb) {
        if (tid < MTILE) {
            int px = tid;
            float offy = offb[(size_t)(2 * kn) * HW + px];
            float offx = offb[(size_t)(2 * kn + 1) * HW + px];
            float ys = (float)(h + (kn / 3) - 1) + offy;
            float xs = (float)(wt + px + (kn % 3) - 1) + offx;
            float y0f = floorf(ys);
            float x0f = floorf(xs);
            int y0 = (int)y0f;
            int x0 = (int)x0f;
            uint32_t yx = ((uint32_t)(uint16_t)(int16_t)y0)
                        | (((uint32_t)(uint16_t)(int16_t)x0) << 16);
            uint32_t ll = pack_f16x2(ys - y0f, xs - x0f);
            *(uint2*)&spb[px * 2] = make_uint2(yx, ll);
        }
    };

    auto gather = [&](uint32_t* ssm, const uint32_t* spb) {
        uint4 z4 = make_uint4(0, 0, 0, 0);
#pragma unroll
        for (int s = 0; s < 4; s++) {
            int px = px0 + 4 * s + quarter;
            uint2 pp = *(const uint2*)&spb[px * 2];
            int y0 = (int)(short)(pp.x & 0xFFFF);
            int x0 = (int)(short)(pp.x >> 16);
            __half2 llh = *(__half2*)&pp.y;
            float ly = __low2float(llh);
            float lx = __high2float(llh);
            float hy = 1.f - ly, hx = 1.f - lx;
            __half2 w00h = __float2half2_rn(hy * hx);
            __half2 w01h = __float2half2_rn(hy * lx);
            __half2 w10h = __float2half2_rn(ly * hx);
            __half2 w11h = __float2half2_rn(ly * lx);
            bool y0k = ((unsigned)y0 < (unsigned)H);
            bool y1k = ((unsigned)(y0 + 1) < (unsigned)H);
            bool x0k = ((unsigned)x0 < (unsigned)W);
            bool x1k = ((unsigned)(x0 + 1) < (unsigned)W);
            const uint4* base = xh4 + ((ptrdiff_t)y0 * W + x0) * (Cin / 8);
            uint4 v00 = (y0k && x0k) ? base[0] : z4;
            uint4 v01 = (y0k && x1k) ? base[Cin / 8] : z4;
            uint4 v10 = (y1k && x0k) ? base[(ptrdiff_t)W * (Cin / 8)] : z4;
            uint4 v11 = (y1k && x1k) ? base[(ptrdiff_t)(W + 1) * (Cin / 8)] : z4;
            uint4 res;
            res.x = bil4(v00.x, v01.x, v10.x, v11.x, w00h, w01h, w10h, w11h);
            res.y = bil4(v00.y, v01.y, v10.y, v11.y, w00h, w01h, w10h, w11h);
            res.z = bil4(v00.z, v01.z, v10.z, v11.z, w00h, w01h, w10h, w11h);
            res.w = bil4(v00.w, v01.w, v10.w, v11.w, w00h, w01h, w10h, w11h);
            *(uint4*)&ssm[px * SH32 + cl8 * 4] = res;
        }
    };

    auto mmaTap = [&](int k, const uint32_t* ssm) {
#pragma unroll
        for (int kk = 0; kk < 4; kk++) {
            int kb = kk << 3;
            uint32_t a[2][4];
#pragma unroll
            for (int mi = 0; mi < 2; mi++) {
                const uint32_t* ar = ssm + (warp_m + 16 * mi + g) * SH32 + kb + r;
                a[mi][0] = ar[0];
                a[mi][1] = ar[8 * SH32];
                a[mi][2] = ar[4];
                a[mi][3] = ar[8 * SH32 + 4];
            }
            uint32_t bb[4][2];
#pragma unroll
            for (int ni = 0; ni < 4; ni++) {
                uint2 v = wfb[((size_t)((k * 8 + nb + ni) * 4 + kk)) * 32];
                bb[ni][0] = v.x;
                bb[ni][1] = v.y;
            }
#pragma unroll
            for (int mi = 0; mi < 2; mi++)
#pragma unroll
                for (int ni = 0; ni < 4; ni++)
                    mma_f16(acc[mi][ni], a[mi], bb[ni]);
        }
    };

    // prologue
    computeSp(0, spB[0]);
    __syncthreads();
    gather(ssmB[0], spB[0]);
    computeSp(1, spB[1]);
    __syncthreads();

    // pipelined mainloop: one sync per tap
#pragma unroll
    for (int k = 0; k < 9; k++) {
        if (k < 8) {
            gather(ssmB[(k + 1) & 1], spB[(k + 1) & 1]);
            if (k < 7) computeSp(k + 2, spB[k & 1]);
        }
        mmaTap(k, ssmB[k & 1]);
        __syncthreads();
    }

    // epilogue: bias + direct stores (NCHW out)
#pragma unroll
    for (int ni = 0; ni < 4; ni++) {
        int o = warp_n + ni * 8 + 2 * r;
        float bo0 = b_def[o];
        float bo1 = b_def[o + 1];
        float* ob0 = out + ((size_t)(b * OUTC + o)) * HW + h * W + wt;
        float* ob1 = ob0 + HW;
#pragma unroll
        for (int mi = 0; mi < 2; mi++) {
            int px = warp_m + mi * 16 + g;
            ob0[px]     = acc[mi][ni][0] + bo0;
            ob1[px]     = acc[mi][ni][1] + bo1;
            ob0[px + 8] = acc[mi][ni][2] + bo0;
            ob1[px + 8] = acc[mi][ni][3] + bo1;
        }
    }
}

// ---------------------------------------------------------------------------
extern "C" void kernel_launch(void* const* d_in, const int* in_sizes, int n_in,
                              void* d_out, int out_size)
{
    const float* x     = (const float*)d_in[0];
    const float* w_off = (const float*)d_in[1];
    const float* b_off = (const float*)d_in[2];
    const float* w_def = (const float*)d_in[3];
    const float* b_def = (const float*)d_in[4];
    float* out = (float*)d_out;

    cudaFuncSetAttribute(deform_kernel,
                         cudaFuncAttributeMaxDynamicSharedMemorySize, DSMEM_BYTES);
    cudaFuncSetAttribute(offsets_kernel,
                         cudaFuncAttributeMaxDynamicSharedMemorySize, OFF_DSMEM);

    int prep_items = 9 * 8 * 4 * 32 + 9 * OJ * Cin;
    prep_fused_kernel<<<(prep_items + 255) / 256, 256>>>(w_def, w_off);
    transpose_x_kernel<<<Bsz * H * (W / 32), 256>>>(x);
    offsets_kernel<<<Bsz * H * (W / MTILE), 256, OFF_DSMEM>>>(b_off);
    deform_kernel<<<Bsz * H * (W / MTILE), 256, DSMEM_BYTES>>>(b_def, out);
}